// round 1
// baseline (speedup 1.0000x reference)
#include <cuda_runtime.h>

// Problem constants
#define B_    16
#define C_    512
#define HW_   784          // 28*28
#define P_    4
#define K_    2048
#define D_    128
#define N_    12544        // B_*HW_
#define NP_   50176        // N_*P_
#define TN    64           // n-rows per CTA tile (12544 = 196*64)
#define TK    64           // k-chunk
#define NTILE 196

// d_out layout: [zq_out (6422528 f32)] [q_loss (1 f32)] [distance_prob (N_*P_*K_ f32)]
#define LOSS_OFF 6422528
#define PROB_OFF 6422529

// Scratch (no allocations allowed)
__device__ float g_sc[P_ * K_];        // ||codebook row||^2
__device__ float g_minD[NP_];          // per (n*4+p) min dist
__device__ int   g_idx[NP_];           // per (n*4+p) argmin k
__device__ float g_losspart[NTILE * P_];

// ---------------------------------------------------------------------------
// K0: per-codeword squared norm, sequential fp32 sum (mul then add, no fma,
// to mimic reference's separate square+reduce).
__global__ void k_sc(const float* __restrict__ cb) {
    int t = blockIdx.x * 256 + threadIdx.x;        // 0..8191 = p*K_+k
    const float* row = cb + (size_t)t * D_;
    float s = 0.f;
    for (int j = 0; j < D_; j++) {
        float q = __fmul_rn(row[j], row[j]);
        s = __fadd_rn(s, q);
    }
    g_sc[t] = s;
}

// ---------------------------------------------------------------------------
// K1: main GEMM-ish pass. Grid (196, 4). 256 threads. Dynamic smem.
// Computes dist = fl( fl(sz + sc) - 2*dot ) exactly like the reference's
// elementwise op chain (2*dot is exact in fp32, so one FFMA == two-op ref).
// Writes raw dist into the prob region, tracks per-row (min, argmin) with
// first-index tie-break.
__global__ void __launch_bounds__(256)
k_main(const float* __restrict__ z, const float* __restrict__ cb,
       float* __restrict__ out) {
    extern __shared__ float sm[];
    float* zs  = sm;                       // [TN][D_+4]
    float* cs  = zs + TN * (D_ + 4);       // [TK][D_+4]
    float* sz  = cs + TK * (D_ + 4);       // [TN]
    float* scs = sz + TN;                  // [TK]

    const int tile = blockIdx.x;
    const int p    = blockIdx.y;
    const int tid  = threadIdx.x;
    const int n0   = tile * TN;

    // Load z tile: zs[r][j] = z[b, p*128+j, hw], coalesced over r.
    for (int e = tid; e < TN * D_; e += 256) {
        int j = e >> 6;            // e / 64
        int r = e & 63;
        int n = n0 + r;
        int b = n / HW_;
        int hw = n - b * HW_;
        zs[r * (D_ + 4) + j] = z[(size_t)(b * C_ + p * D_ + j) * HW_ + hw];
    }
    __syncthreads();

    // sz[r] = sequential fp32 sum of squares (mul+add, matching ref structure)
    if (tid < TN) {
        const float* zr = zs + tid * (D_ + 4);
        float s = 0.f;
        for (int j = 0; j < D_; j++) {
            float q = __fmul_rn(zr[j], zr[j]);
            s = __fadd_rn(s, q);
        }
        sz[tid] = s;
    }

    const int tk = tid & 15;
    const int tn = tid >> 4;

    float minv[4];
    int   mink[4];
#pragma unroll
    for (int i = 0; i < 4; i++) { minv[i] = 3.4e38f; mink[i] = 0; }

    float* prob = out + PROB_OFF;

    for (int kc = 0; kc < K_; kc += TK) {
        __syncthreads();   // protect cs/scs reuse + sz visibility
        // Load codebook chunk (coalesced float4 over d)
        for (int e = tid; e < TK * (D_ / 4); e += 256) {
            int kr = e >> 5;
            int j4 = e & 31;
            float4 v = *(const float4*)(cb + ((size_t)(p * K_ + kc + kr) * D_) + j4 * 4);
            float* dst = cs + kr * (D_ + 4) + j4 * 4;
            dst[0] = v.x; dst[1] = v.y; dst[2] = v.z; dst[3] = v.w;
        }
        if (tid < TK) scs[tid] = g_sc[p * K_ + kc + tid];
        __syncthreads();

        // 4x4 register microtile, float4 over d
        float acc[4][4];
#pragma unroll
        for (int i = 0; i < 4; i++)
#pragma unroll
            for (int j = 0; j < 4; j++) acc[i][j] = 0.f;

#pragma unroll 4
        for (int d4 = 0; d4 < D_; d4 += 4) {
            float4 zv[4], cv[4];
#pragma unroll
            for (int i = 0; i < 4; i++)
                zv[i] = *(const float4*)(zs + (tn + 16 * i) * (D_ + 4) + d4);
#pragma unroll
            for (int j = 0; j < 4; j++)
                cv[j] = *(const float4*)(cs + (tk + 16 * j) * (D_ + 4) + d4);
#pragma unroll
            for (int i = 0; i < 4; i++) {
#pragma unroll
                for (int j = 0; j < 4; j++) {
                    acc[i][j] = fmaf(zv[i].x, cv[j].x, acc[i][j]);
                    acc[i][j] = fmaf(zv[i].y, cv[j].y, acc[i][j]);
                    acc[i][j] = fmaf(zv[i].z, cv[j].z, acc[i][j]);
                    acc[i][j] = fmaf(zv[i].w, cv[j].w, acc[i][j]);
                }
            }
        }

        // Emit dist + running argmin (k scanned ascending per thread)
#pragma unroll
        for (int i = 0; i < 4; i++) {
            int n = n0 + tn + 16 * i;
            float szi = sz[tn + 16 * i];
#pragma unroll
            for (int j = 0; j < 4; j++) {
                int kl = tk + 16 * j;
                int k  = kc + kl;
                float szc  = __fadd_rn(szi, scs[kl]);          // fl(sz+sc), as ref
                float dist = __fmaf_rn(-2.f, acc[i][j], szc);  // == fl(szc - fl(2*dot))
                prob[(size_t)n * 8192 + p * 2048 + k] = dist;
                if (dist < minv[i]) { minv[i] = dist; mink[i] = k; }
            }
        }
    }

    // Cross-thread argmin reduce: 16 lanes (same tn) are contiguous in a warp.
#pragma unroll
    for (int i = 0; i < 4; i++) {
        float bv = minv[i];
        int   bk = mink[i];
        for (int off = 8; off; off >>= 1) {
            float v2 = __shfl_down_sync(0xffffffffu, bv, off, 16);
            int   k2 = __shfl_down_sync(0xffffffffu, bk, off, 16);
            if (v2 < bv || (v2 == bv && k2 < bk)) { bv = v2; bk = k2; }
        }
        if (tk == 0) {
            int n = n0 + tn + 16 * i;
            g_minD[n * 4 + p] = bv;
            g_idx[n * 4 + p]  = bk;
        }
    }
}

// ---------------------------------------------------------------------------
// K2: in-place softmax normalize. One 64-thread group per row (4 rows/CTA).
// e = exp(2*(minD - dist)) matches ref's exp(x - max) bit-for-bit in structure
// (scaling by 2 commutes with rounding).
__global__ void __launch_bounds__(256)
k_norm(float* __restrict__ out) {
    int g      = threadIdx.x >> 6;
    int lane64 = threadIdx.x & 63;
    int rho    = blockIdx.x * 4 + g;                 // rho = n*4 + p
    float* row = out + PROB_OFF + (size_t)rho * 2048;
    float m = g_minD[rho];

    float e[32];
    float s = 0.f;
#pragma unroll 4
    for (int ii = 0; ii < 32; ii++) {
        float dist = row[lane64 + 64 * ii];
        float ev = expf(2.f * (m - dist));
        e[ii] = ev;
        s += ev;
    }
    // warp reduce (each warp holds 32 partials of ONE row)
    for (int o = 16; o; o >>= 1) s += __shfl_down_sync(0xffffffffu, s, o);
    __shared__ float wsum[8];
    if ((threadIdx.x & 31) == 0) wsum[threadIdx.x >> 5] = s;
    __syncthreads();
    float S = wsum[2 * g] + wsum[2 * g + 1];
    float inv = 1.0f / S;
#pragma unroll 4
    for (int ii = 0; ii < 32; ii++) row[lane64 + 64 * ii] = e[ii] * inv;
}

// ---------------------------------------------------------------------------
// K3: zq_out (straight-through, fl(zf + fl(zq - zf))) + per-CTA loss partials.
__global__ void __launch_bounds__(256)
k_zq(const float* __restrict__ z, const float* __restrict__ cb,
     float* __restrict__ out) {
    __shared__ float cz[TN][D_];
    __shared__ int   sidx[TN];
    __shared__ float lred[256];

    const int tile = blockIdx.x;
    const int p    = blockIdx.y;
    const int tid  = threadIdx.x;
    const int n0   = tile * TN;

    if (tid < TN) sidx[tid] = g_idx[(n0 + tid) * 4 + p];
    __syncthreads();

    for (int e = tid; e < TN * (D_ / 4); e += 256) {
        int r  = e >> 5;
        int j4 = e & 31;
        float4 v = *(const float4*)(cb + ((size_t)(p * K_ + sidx[r]) * D_) + j4 * 4);
        cz[r][j4 * 4 + 0] = v.x; cz[r][j4 * 4 + 1] = v.y;
        cz[r][j4 * 4 + 2] = v.z; cz[r][j4 * 4 + 3] = v.w;
    }
    __syncthreads();

    float ls = 0.f;
    for (int e = tid; e < TN * D_; e += 256) {
        int j = e >> 6;
        int r = e & 63;
        int n = n0 + r;
        int b = n / HW_;
        int hw = n - b * HW_;
        size_t ga = (size_t)(b * C_ + p * D_ + j) * HW_ + hw;
        float zf = z[ga];
        float d  = __fsub_rn(cz[r][j], zf);      // fl(zq - zf)
        out[ga]  = __fadd_rn(zf, d);             // zq_st
        ls = __fadd_rn(ls, __fmul_rn(d, d));
    }
    lred[tid] = ls;
    __syncthreads();
    for (int o = 128; o; o >>= 1) {
        if (tid < o) lred[tid] += lred[tid + o];
        __syncthreads();
    }
    if (tid == 0) g_losspart[p * NTILE + tile] = lred[0];
}

// ---------------------------------------------------------------------------
// K4: final deterministic loss reduction. q = m + fl(0.25*m).
__global__ void k_loss(float* __restrict__ out) {
    __shared__ float s[256];
    int tid = threadIdx.x;
    float a = 0.f;
    for (int e = tid; e < NTILE * P_; e += 256) a += g_losspart[e];
    s[tid] = a;
    __syncthreads();
    for (int o = 128; o; o >>= 1) {
        if (tid < o) s[tid] += s[tid + o];
        __syncthreads();
    }
    if (tid == 0) {
        float m = s[0] / 6422528.0f;
        out[LOSS_OFF] = __fadd_rn(m, __fmul_rn(0.25f, m));
    }
}

// ---------------------------------------------------------------------------
extern "C" void kernel_launch(void* const* d_in, const int* in_sizes, int n_in,
                              void* d_out, int out_size) {
    const float* z  = (const float*)d_in[0];   // [16,512,28,28]
    const float* cb = (const float*)d_in[1];   // [4,2048,128]
    float* out = (float*)d_out;

    const int smem_k1 = (TN * (D_ + 4) + TK * (D_ + 4) + TN + TK) * (int)sizeof(float);
    cudaFuncSetAttribute(k_main, cudaFuncAttributeMaxDynamicSharedMemorySize, smem_k1);

    k_sc<<<32, 256>>>(cb);
    k_main<<<dim3(NTILE, P_), 256, smem_k1>>>(z, cb, out);
    k_norm<<<N_, 256>>>(out);
    k_zq<<<dim3(NTILE, P_), 256>>>(z, cb, out);
    k_loss<<<1, 256>>>(out);
}

// round 2
// speedup vs baseline: 1.5423x; 1.5423x over previous
#include <cuda_runtime.h>

// Problem constants
#define B_    16
#define C_    512
#define HW_   784          // 28*28
#define P_    4
#define K_    2048
#define D_    128
#define N_    12544        // B_*HW_
#define NP_   50176        // N_*P_
#define TN    64           // n-rows per CTA tile (12544 = 196*64)
#define TK    64           // k-chunk
#define NTILE 196

// d_out layout: [zq_out (6422528 f32)] [q_loss (1 f32)] [distance_prob (N_*P_*K_ f32)]
#define LOSS_OFF 6422528
#define PROB_OFF 6422529

// Scratch (no allocations allowed)
__device__ float g_sc[P_ * K_];        // ||codebook row||^2
__device__ float g_minD[NP_];          // per (n*4+p) min dist
__device__ int   g_idx[NP_];           // per (n*4+p) argmin k
__device__ float g_losspart[NTILE * P_];

// ---------------------------------------------------------------------------
// K0: per-codeword squared norm, sequential fp32 sum (mul then add, no fma,
// to mimic reference's separate square+reduce).
__global__ void k_sc(const float* __restrict__ cb) {
    int t = blockIdx.x * 256 + threadIdx.x;        // 0..8191 = p*K_+k
    const float* row = cb + (size_t)t * D_;
    float s = 0.f;
    for (int j = 0; j < D_; j++) {
        float q = __fmul_rn(row[j], row[j]);
        s = __fadd_rn(s, q);
    }
    g_sc[t] = s;
}

// ---------------------------------------------------------------------------
// K1: main GEMM-ish pass. Grid (196, 4). 256 threads. Dynamic smem.
// Computes dist = fl( fl(sz + sc) - 2*dot ) exactly like the reference's
// elementwise op chain (2*dot is exact in fp32, so one FFMA == two-op ref).
// Writes raw dist into the prob region, tracks per-row (min, argmin) with
// first-index tie-break.
__global__ void __launch_bounds__(256)
k_main(const float* __restrict__ z, const float* __restrict__ cb,
       float* __restrict__ out) {
    extern __shared__ float sm[];
    float* zs  = sm;                       // [TN][D_+4]
    float* cs  = zs + TN * (D_ + 4);       // [TK][D_+4]
    float* sz  = cs + TK * (D_ + 4);       // [TN]
    float* scs = sz + TN;                  // [TK]

    const int tile = blockIdx.x;
    const int p    = blockIdx.y;
    const int tid  = threadIdx.x;
    const int n0   = tile * TN;

    // Load z tile: zs[r][j] = z[b, p*128+j, hw], coalesced over r.
    for (int e = tid; e < TN * D_; e += 256) {
        int j = e >> 6;            // e / 64
        int r = e & 63;
        int n = n0 + r;
        int b = n / HW_;
        int hw = n - b * HW_;
        zs[r * (D_ + 4) + j] = z[(size_t)(b * C_ + p * D_ + j) * HW_ + hw];
    }
    __syncthreads();

    // sz[r] = sequential fp32 sum of squares (mul+add, matching ref structure)
    if (tid < TN) {
        const float* zr = zs + tid * (D_ + 4);
        float s = 0.f;
        for (int j = 0; j < D_; j++) {
            float q = __fmul_rn(zr[j], zr[j]);
            s = __fadd_rn(s, q);
        }
        sz[tid] = s;
    }

    const int tk = tid & 15;
    const int tn = tid >> 4;

    float minv[4];
    int   mink[4];
#pragma unroll
    for (int i = 0; i < 4; i++) { minv[i] = 3.4e38f; mink[i] = 0; }

    float* prob = out + PROB_OFF;

    for (int kc = 0; kc < K_; kc += TK) {
        __syncthreads();   // protect cs/scs reuse + sz visibility
        // Load codebook chunk (coalesced float4 over d)
        for (int e = tid; e < TK * (D_ / 4); e += 256) {
            int kr = e >> 5;
            int j4 = e & 31;
            float4 v = *(const float4*)(cb + ((size_t)(p * K_ + kc + kr) * D_) + j4 * 4);
            float* dst = cs + kr * (D_ + 4) + j4 * 4;
            dst[0] = v.x; dst[1] = v.y; dst[2] = v.z; dst[3] = v.w;
        }
        if (tid < TK) scs[tid] = g_sc[p * K_ + kc + tid];
        __syncthreads();

        // 4x4 register microtile, float4 over d
        float acc[4][4];
#pragma unroll
        for (int i = 0; i < 4; i++)
#pragma unroll
            for (int j = 0; j < 4; j++) acc[i][j] = 0.f;

#pragma unroll 4
        for (int d4 = 0; d4 < D_; d4 += 4) {
            float4 zv[4], cv[4];
#pragma unroll
            for (int i = 0; i < 4; i++)
                zv[i] = *(const float4*)(zs + (tn + 16 * i) * (D_ + 4) + d4);
#pragma unroll
            for (int j = 0; j < 4; j++)
                cv[j] = *(const float4*)(cs + (tk + 16 * j) * (D_ + 4) + d4);
#pragma unroll
            for (int i = 0; i < 4; i++) {
#pragma unroll
                for (int j = 0; j < 4; j++) {
                    acc[i][j] = fmaf(zv[i].x, cv[j].x, acc[i][j]);
                    acc[i][j] = fmaf(zv[i].y, cv[j].y, acc[i][j]);
                    acc[i][j] = fmaf(zv[i].z, cv[j].z, acc[i][j]);
                    acc[i][j] = fmaf(zv[i].w, cv[j].w, acc[i][j]);
                }
            }
        }

        // Emit dist + running argmin (k scanned ascending per thread)
#pragma unroll
        for (int i = 0; i < 4; i++) {
            int n = n0 + tn + 16 * i;
            float szi = sz[tn + 16 * i];
#pragma unroll
            for (int j = 0; j < 4; j++) {
                int kl = tk + 16 * j;
                int k  = kc + kl;
                float szc  = __fadd_rn(szi, scs[kl]);          // fl(sz+sc), as ref
                float dist = __fmaf_rn(-2.f, acc[i][j], szc);  // == fl(szc - fl(2*dot))
                prob[(size_t)n * 8192 + p * 2048 + k] = dist;
                if (dist < minv[i]) { minv[i] = dist; mink[i] = k; }
            }
        }
    }

    // Cross-thread argmin reduce: 16 lanes (same tn) are contiguous in a warp.
#pragma unroll
    for (int i = 0; i < 4; i++) {
        float bv = minv[i];
        int   bk = mink[i];
        for (int off = 8; off; off >>= 1) {
            float v2 = __shfl_down_sync(0xffffffffu, bv, off, 16);
            int   k2 = __shfl_down_sync(0xffffffffu, bk, off, 16);
            if (v2 < bv || (v2 == bv && k2 < bk)) { bv = v2; bk = k2; }
        }
        if (tk == 0) {
            int n = n0 + tn + 16 * i;
            g_minD[n * 4 + p] = bv;
            g_idx[n * 4 + p]  = bk;
        }
    }
}

// ---------------------------------------------------------------------------
// K2: in-place softmax normalize. One 64-thread group per row (4 rows/CTA).
// e = exp(2*(minD - dist)) matches ref's exp(x - max) bit-for-bit in structure
// (scaling by 2 commutes with rounding).
__global__ void __launch_bounds__(256)
k_norm(float* __restrict__ out) {
    int g      = threadIdx.x >> 6;
    int lane64 = threadIdx.x & 63;
    int rho    = blockIdx.x * 4 + g;                 // rho = n*4 + p
    float* row = out + PROB_OFF + (size_t)rho * 2048;
    float m = g_minD[rho];

    float e[32];
    float s = 0.f;
#pragma unroll 4
    for (int ii = 0; ii < 32; ii++) {
        float dist = row[lane64 + 64 * ii];
        float ev = expf(2.f * (m - dist));
        e[ii] = ev;
        s += ev;
    }
    // warp reduce (each warp holds 32 partials of ONE row)
    for (int o = 16; o; o >>= 1) s += __shfl_down_sync(0xffffffffu, s, o);
    __shared__ float wsum[8];
    if ((threadIdx.x & 31) == 0) wsum[threadIdx.x >> 5] = s;
    __syncthreads();
    float S = wsum[2 * g] + wsum[2 * g + 1];
    float inv = 1.0f / S;
#pragma unroll 4
    for (int ii = 0; ii < 32; ii++) row[lane64 + 64 * ii] = e[ii] * inv;
}

// ---------------------------------------------------------------------------
// K3: zq_out (straight-through, fl(zf + fl(zq - zf))) + per-CTA loss partials.
__global__ void __launch_bounds__(256)
k_zq(const float* __restrict__ z, const float* __restrict__ cb,
     float* __restrict__ out) {
    __shared__ float cz[TN][D_];
    __shared__ int   sidx[TN];
    __shared__ float lred[256];

    const int tile = blockIdx.x;
    const int p    = blockIdx.y;
    const int tid  = threadIdx.x;
    const int n0   = tile * TN;

    if (tid < TN) sidx[tid] = g_idx[(n0 + tid) * 4 + p];
    __syncthreads();

    for (int e = tid; e < TN * (D_ / 4); e += 256) {
        int r  = e >> 5;
        int j4 = e & 31;
        float4 v = *(const float4*)(cb + ((size_t)(p * K_ + sidx[r]) * D_) + j4 * 4);
        cz[r][j4 * 4 + 0] = v.x; cz[r][j4 * 4 + 1] = v.y;
        cz[r][j4 * 4 + 2] = v.z; cz[r][j4 * 4 + 3] = v.w;
    }
    __syncthreads();

    float ls = 0.f;
    for (int e = tid; e < TN * D_; e += 256) {
        int j = e >> 6;
        int r = e & 63;
        int n = n0 + r;
        int b = n / HW_;
        int hw = n - b * HW_;
        size_t ga = (size_t)(b * C_ + p * D_ + j) * HW_ + hw;
        float zf = z[ga];
        float d  = __fsub_rn(cz[r][j], zf);      // fl(zq - zf)
        out[ga]  = __fadd_rn(zf, d);             // zq_st
        ls = __fadd_rn(ls, __fmul_rn(d, d));
    }
    lred[tid] = ls;
    __syncthreads();
    for (int o = 128; o; o >>= 1) {
        if (tid < o) lred[tid] += lred[tid + o];
        __syncthreads();
    }
    if (tid == 0) g_losspart[p * NTILE + tile] = lred[0];
}

// ---------------------------------------------------------------------------
// K4: final deterministic loss reduction. q = m + fl(0.25*m).
__global__ void k_loss(float* __restrict__ out) {
    __shared__ float s[256];
    int tid = threadIdx.x;
    float a = 0.f;
    for (int e = tid; e < NTILE * P_; e += 256) a += g_losspart[e];
    s[tid] = a;
    __syncthreads();
    for (int o = 128; o; o >>= 1) {
        if (tid < o) s[tid] += s[tid + o];
        __syncthreads();
    }
    if (tid == 0) {
        float m = s[0] / 6422528.0f;
        out[LOSS_OFF] = __fadd_rn(m, __fmul_rn(0.25f, m));
    }
}

// ---------------------------------------------------------------------------
extern "C" void kernel_launch(void* const* d_in, const int* in_sizes, int n_in,
                              void* d_out, int out_size) {
    const float* z  = (const float*)d_in[0];   // [16,512,28,28]
    const float* cb = (const float*)d_in[1];   // [4,2048,128]
    float* out = (float*)d_out;

    const int smem_k1 = (TN * (D_ + 4) + TK * (D_ + 4) + TN + TK) * (int)sizeof(float);
    cudaFuncSetAttribute(k_main, cudaFuncAttributeMaxDynamicSharedMemorySize, smem_k1);

    k_sc<<<32, 256>>>(cb);
    k_main<<<dim3(NTILE, P_), 256, smem_k1>>>(z, cb, out);
    k_norm<<<N_, 256>>>(out);
    k_zq<<<dim3(NTILE, P_), 256>>>(z, cb, out);
    k_loss<<<1, 256>>>(out);
}

// round 3
// speedup vs baseline: 1.5467x; 1.0029x over previous
#include <cuda_runtime.h>

// Problem constants
#define B_    16
#define C_    512
#define HW_   784          // 28*28
#define P_    4
#define K_    2048
#define D_    128
#define N_    12544        // B_*HW_
#define NP_   50176        // N_*P_
#define TN    64           // n-rows per CTA tile (12544 = 196*64)
#define TK    64           // k-chunk
#define NTILE 196

// d_out layout: [zq_out (6422528 f32)] [q_loss (1 f32)] [distance_prob (N_*P_*K_ f32)]
#define LOSS_OFF 6422528
#define PROB_OFF 6422529

// Scratch (no allocations allowed)
__device__ float g_sc[P_ * K_];        // ||codebook row||^2
__device__ float g_minD[NP_];          // per (n*4+p) min dist
__device__ int   g_idx[NP_];           // per (n*4+p) argmin k
__device__ float g_losspart[NTILE * P_];

// ---------------------------------------------------------------------------
// K0: per-codeword squared norm, sequential fp32 sum (mul then add, no fma,
// to mimic reference's separate square+reduce).
__global__ void k_sc(const float* __restrict__ cb) {
    int t = blockIdx.x * 256 + threadIdx.x;        // 0..8191 = p*K_+k
    const float* row = cb + (size_t)t * D_;
    float s = 0.f;
    for (int j = 0; j < D_; j++) {
        float q = __fmul_rn(row[j], row[j]);
        s = __fadd_rn(s, q);
    }
    g_sc[t] = s;
}

// ---------------------------------------------------------------------------
// K1: main GEMM-ish pass. Grid (196, 4). 256 threads. Dynamic smem.
// Computes dist = fl( fl(sz + sc) - 2*dot ) exactly like the reference's
// elementwise op chain (2*dot is exact in fp32, so one FFMA == two-op ref).
// Writes raw dist into the prob region, tracks per-row (min, argmin) with
// first-index tie-break.
__global__ void __launch_bounds__(256)
k_main(const float* __restrict__ z, const float* __restrict__ cb,
       float* __restrict__ out) {
    extern __shared__ float sm[];
    float* zs  = sm;                       // [TN][D_+4]
    float* cs  = zs + TN * (D_ + 4);       // [TK][D_+4]
    float* sz  = cs + TK * (D_ + 4);       // [TN]
    float* scs = sz + TN;                  // [TK]

    const int tile = blockIdx.x;
    const int p    = blockIdx.y;
    const int tid  = threadIdx.x;
    const int n0   = tile * TN;

    // Load z tile: zs[r][j] = z[b, p*128+j, hw], coalesced over r.
    for (int e = tid; e < TN * D_; e += 256) {
        int j = e >> 6;            // e / 64
        int r = e & 63;
        int n = n0 + r;
        int b = n / HW_;
        int hw = n - b * HW_;
        zs[r * (D_ + 4) + j] = z[(size_t)(b * C_ + p * D_ + j) * HW_ + hw];
    }
    __syncthreads();

    // sz[r] = sequential fp32 sum of squares (mul+add, matching ref structure)
    if (tid < TN) {
        const float* zr = zs + tid * (D_ + 4);
        float s = 0.f;
        for (int j = 0; j < D_; j++) {
            float q = __fmul_rn(zr[j], zr[j]);
            s = __fadd_rn(s, q);
        }
        sz[tid] = s;
    }

    const int tk = tid & 15;
    const int tn = tid >> 4;

    float minv[4];
    int   mink[4];
#pragma unroll
    for (int i = 0; i < 4; i++) { minv[i] = 3.4e38f; mink[i] = 0; }

    float* prob = out + PROB_OFF;

    for (int kc = 0; kc < K_; kc += TK) {
        __syncthreads();   // protect cs/scs reuse + sz visibility
        // Load codebook chunk (coalesced float4 over d)
        for (int e = tid; e < TK * (D_ / 4); e += 256) {
            int kr = e >> 5;
            int j4 = e & 31;
            float4 v = *(const float4*)(cb + ((size_t)(p * K_ + kc + kr) * D_) + j4 * 4);
            float* dst = cs + kr * (D_ + 4) + j4 * 4;
            dst[0] = v.x; dst[1] = v.y; dst[2] = v.z; dst[3] = v.w;
        }
        if (tid < TK) scs[tid] = g_sc[p * K_ + kc + tid];
        __syncthreads();

        // 4x4 register microtile, float4 over d
        float acc[4][4];
#pragma unroll
        for (int i = 0; i < 4; i++)
#pragma unroll
            for (int j = 0; j < 4; j++) acc[i][j] = 0.f;

#pragma unroll 4
        for (int d4 = 0; d4 < D_; d4 += 4) {
            float4 zv[4], cv[4];
#pragma unroll
            for (int i = 0; i < 4; i++)
                zv[i] = *(const float4*)(zs + (tn + 16 * i) * (D_ + 4) + d4);
#pragma unroll
            for (int j = 0; j < 4; j++)
                cv[j] = *(const float4*)(cs + (tk + 16 * j) * (D_ + 4) + d4);
#pragma unroll
            for (int i = 0; i < 4; i++) {
#pragma unroll
                for (int j = 0; j < 4; j++) {
                    acc[i][j] = fmaf(zv[i].x, cv[j].x, acc[i][j]);
                    acc[i][j] = fmaf(zv[i].y, cv[j].y, acc[i][j]);
                    acc[i][j] = fmaf(zv[i].z, cv[j].z, acc[i][j]);
                    acc[i][j] = fmaf(zv[i].w, cv[j].w, acc[i][j]);
                }
            }
        }

        // Emit dist + running argmin (k scanned ascending per thread)
#pragma unroll
        for (int i = 0; i < 4; i++) {
            int n = n0 + tn + 16 * i;
            float szi = sz[tn + 16 * i];
#pragma unroll
            for (int j = 0; j < 4; j++) {
                int kl = tk + 16 * j;
                int k  = kc + kl;
                float szc  = __fadd_rn(szi, scs[kl]);          // fl(sz+sc), as ref
                float dist = __fmaf_rn(-2.f, acc[i][j], szc);  // == fl(szc - fl(2*dot))
                prob[(size_t)n * 8192 + p * 2048 + k] = dist;
                if (dist < minv[i]) { minv[i] = dist; mink[i] = k; }
            }
        }
    }

    // Cross-thread argmin reduce: 16 lanes (same tn) are contiguous in a warp.
#pragma unroll
    for (int i = 0; i < 4; i++) {
        float bv = minv[i];
        int   bk = mink[i];
        for (int off = 8; off; off >>= 1) {
            float v2 = __shfl_down_sync(0xffffffffu, bv, off, 16);
            int   k2 = __shfl_down_sync(0xffffffffu, bk, off, 16);
            if (v2 < bv || (v2 == bv && k2 < bk)) { bv = v2; bk = k2; }
        }
        if (tk == 0) {
            int n = n0 + tn + 16 * i;
            g_minD[n * 4 + p] = bv;
            g_idx[n * 4 + p]  = bk;
        }
    }
}

// ---------------------------------------------------------------------------
// K2: in-place softmax normalize. One 64-thread group per row (4 rows/CTA).
// e = exp(2*(minD - dist)) matches ref's exp(x - max) bit-for-bit in structure
// (scaling by 2 commutes with rounding).
__global__ void __launch_bounds__(256)
k_norm(float* __restrict__ out) {
    int g      = threadIdx.x >> 6;
    int lane64 = threadIdx.x & 63;
    int rho    = blockIdx.x * 4 + g;                 // rho = n*4 + p
    float* row = out + PROB_OFF + (size_t)rho * 2048;
    float m = g_minD[rho];

    float e[32];
    float s = 0.f;
#pragma unroll 4
    for (int ii = 0; ii < 32; ii++) {
        float dist = row[lane64 + 64 * ii];
        float ev = expf(2.f * (m - dist));
        e[ii] = ev;
        s += ev;
    }
    // warp reduce (each warp holds 32 partials of ONE row)
    for (int o = 16; o; o >>= 1) s += __shfl_down_sync(0xffffffffu, s, o);
    __shared__ float wsum[8];
    if ((threadIdx.x & 31) == 0) wsum[threadIdx.x >> 5] = s;
    __syncthreads();
    float S = wsum[2 * g] + wsum[2 * g + 1];
    float inv = 1.0f / S;
#pragma unroll 4
    for (int ii = 0; ii < 32; ii++) row[lane64 + 64 * ii] = e[ii] * inv;
}

// ---------------------------------------------------------------------------
// K3: zq_out (straight-through, fl(zf + fl(zq - zf))) + per-CTA loss partials.
__global__ void __launch_bounds__(256)
k_zq(const float* __restrict__ z, const float* __restrict__ cb,
     float* __restrict__ out) {
    __shared__ float cz[TN][D_];
    __shared__ int   sidx[TN];
    __shared__ float lred[256];

    const int tile = blockIdx.x;
    const int p    = blockIdx.y;
    const int tid  = threadIdx.x;
    const int n0   = tile * TN;

    if (tid < TN) sidx[tid] = g_idx[(n0 + tid) * 4 + p];
    __syncthreads();

    for (int e = tid; e < TN * (D_ / 4); e += 256) {
        int r  = e >> 5;
        int j4 = e & 31;
        float4 v = *(const float4*)(cb + ((size_t)(p * K_ + sidx[r]) * D_) + j4 * 4);
        cz[r][j4 * 4 + 0] = v.x; cz[r][j4 * 4 + 1] = v.y;
        cz[r][j4 * 4 + 2] = v.z; cz[r][j4 * 4 + 3] = v.w;
    }
    __syncthreads();

    float ls = 0.f;
    for (int e = tid; e < TN * D_; e += 256) {
        int j = e >> 6;
        int r = e & 63;
        int n = n0 + r;
        int b = n / HW_;
        int hw = n - b * HW_;
        size_t ga = (size_t)(b * C_ + p * D_ + j) * HW_ + hw;
        float zf = z[ga];
        float d  = __fsub_rn(cz[r][j], zf);      // fl(zq - zf)
        out[ga]  = __fadd_rn(zf, d);             // zq_st
        ls = __fadd_rn(ls, __fmul_rn(d, d));
    }
    lred[tid] = ls;
    __syncthreads();
    for (int o = 128; o; o >>= 1) {
        if (tid < o) lred[tid] += lred[tid + o];
        __syncthreads();
    }
    if (tid == 0) g_losspart[p * NTILE + tile] = lred[0];
}

// ---------------------------------------------------------------------------
// K4: final deterministic loss reduction. q = m + fl(0.25*m).
__global__ void k_loss(float* __restrict__ out) {
    __shared__ float s[256];
    int tid = threadIdx.x;
    float a = 0.f;
    for (int e = tid; e < NTILE * P_; e += 256) a += g_losspart[e];
    s[tid] = a;
    __syncthreads();
    for (int o = 128; o; o >>= 1) {
        if (tid < o) s[tid] += s[tid + o];
        __syncthreads();
    }
    if (tid == 0) {
        float m = s[0] / 6422528.0f;
        out[LOSS_OFF] = __fadd_rn(m, __fmul_rn(0.25f, m));
    }
}

// ---------------------------------------------------------------------------
extern "C" void kernel_launch(void* const* d_in, const int* in_sizes, int n_in,
                              void* d_out, int out_size) {
    const float* z  = (const float*)d_in[0];   // [16,512,28,28]
    const float* cb = (const float*)d_in[1];   // [4,2048,128]
    float* out = (float*)d_out;

    const int smem_k1 = (TN * (D_ + 4) + TK * (D_ + 4) + TN + TK) * (int)sizeof(float);
    cudaFuncSetAttribute(k_main, cudaFuncAttributeMaxDynamicSharedMemorySize, smem_k1);

    k_sc<<<32, 256>>>(cb);
    k_main<<<dim3(NTILE, P_), 256, smem_k1>>>(z, cb, out);
    k_norm<<<N_, 256>>>(out);
    k_zq<<<dim3(NTILE, P_), 256>>>(z, cb, out);
    k_loss<<<1, 256>>>(out);
}

// round 4
// speedup vs baseline: 1.5568x; 1.0065x over previous
#include <cuda_runtime.h>

// Problem constants
#define B_    16
#define C_    512
#define HW_   784          // 28*28
#define P_    4
#define K_    2048
#define D_    128
#define N_    12544        // B_*HW_
#define NP_   50176        // N_*P_
#define TN    64           // n-rows per CTA tile (12544 = 196*64)
#define TKC   128          // k-chunk
#define NTILE 196

#define ZSTR  132          // z smem row stride (floats), 16B-aligned rows
#define CSTR  130          // c smem row stride (floats), conflict-free LDS.64

// d_out layout: [zq_out (6422528 f32)] [q_loss (1 f32)] [distance_prob (N_*P_*K_ f32)]
#define LOSS_OFF 6422528
#define PROB_OFF 6422529

typedef unsigned long long u64;

__device__ __forceinline__ u64 ffma2(u64 a, u64 b, u64 c) {
    u64 d;
    asm("fma.rn.f32x2 %0, %1, %2, %3;" : "=l"(d) : "l"(a), "l"(b), "l"(c));
    return d;
}
__device__ __forceinline__ float lo32(u64 v) { return __uint_as_float((unsigned)(v & 0xffffffffull)); }
__device__ __forceinline__ float hi32(u64 v) { return __uint_as_float((unsigned)(v >> 32)); }

// Scratch (no allocations allowed)
__device__ float g_sc[P_ * K_];        // ||codebook row||^2
__device__ float g_minD[NP_];          // per (n*4+p) min dist
__device__ int   g_idx[NP_];           // per (n*4+p) argmin k
__device__ float g_losspart[NTILE * P_];

// ---------------------------------------------------------------------------
// K0: per-codeword squared norm, sequential fp32 sum (mul then add, matching
// reference's separate square+reduce structure).
__global__ void k_sc(const float* __restrict__ cb) {
    int t = blockIdx.x * 256 + threadIdx.x;        // 0..8191 = p*K_+k
    const float* row = cb + (size_t)t * D_;
    float s = 0.f;
    for (int j = 0; j < D_; j++) {
        float q = __fmul_rn(row[j], row[j]);
        s = __fadd_rn(s, q);
    }
    g_sc[t] = s;
}

// ---------------------------------------------------------------------------
// K1: main GEMM pass with packed FFMA2 (fma.rn.f32x2).
// Accumulators are packed over d-parity: acc = (sum over even-pair d's,
// sum over odd-pair d's); dot = lo+hi. Both operands are natural
// consecutive-d pairs -> no transpose/duplication needed in smem.
// Grid (196, 4), 256 threads = 16(tk) x 16(tn). Per-thread microtile:
// 4 n-rows x 8 k's. Writes raw dist into prob region, tracks argmin.
__global__ void __launch_bounds__(256, 2)
k_main(const float* __restrict__ z, const float* __restrict__ cb,
       float* __restrict__ out) {
    extern __shared__ float sm[];
    float* zs  = sm;                        // [TN][ZSTR]
    float* cs  = zs + TN * ZSTR;            // [TKC][CSTR]
    float* sz  = cs + TKC * CSTR;           // [TN]
    float* scs = sz + TN;                   // [TKC]

    const int tile = blockIdx.x;
    const int p    = blockIdx.y;
    const int tid  = threadIdx.x;
    const int n0   = tile * TN;

    // Load z tile: zs[r][j] = z[b, p*128+j, hw], coalesced over r.
    for (int e = tid; e < TN * D_; e += 256) {
        int j = e >> 6;            // e / 64
        int r = e & 63;
        int n = n0 + r;
        int b = n / HW_;
        int hw = n - b * HW_;
        zs[r * ZSTR + j] = z[(size_t)(b * C_ + p * D_ + j) * HW_ + hw];
    }
    __syncthreads();

    // sz[r] = sequential fp32 sum of squares (mul+add, matching ref structure)
    if (tid < TN) {
        const float* zr = zs + tid * ZSTR;
        float s = 0.f;
        for (int j = 0; j < D_; j++) {
            float q = __fmul_rn(zr[j], zr[j]);
            s = __fadd_rn(s, q);
        }
        sz[tid] = s;
    }

    const int tk = tid & 15;
    const int tn = tid >> 4;

    float minv[4];
    int   mink[4];
#pragma unroll
    for (int i = 0; i < 4; i++) { minv[i] = 3.4e38f; mink[i] = 0; }

    float* prob = out + PROB_OFF;

    const float* zbase = zs + tn * ZSTR;   // rows tn + 16*i
    const float* cbase = cs + tk * CSTR;   // k = tk + 16*j

    for (int kc = 0; kc < K_; kc += TKC) {
        __syncthreads();   // protect cs/scs reuse + sz visibility
        // Load codebook chunk (coalesced float4 over d)
        for (int e = tid; e < TKC * (D_ / 4); e += 256) {
            int kr = e >> 5;
            int j4 = e & 31;
            float4 v = *(const float4*)(cb + ((size_t)(p * K_ + kc + kr) * D_) + j4 * 4);
            float* dst = cs + kr * CSTR + j4 * 4;
            dst[0] = v.x; dst[1] = v.y; dst[2] = v.z; dst[3] = v.w;
        }
        if (tid < TKC) scs[tid] = g_sc[p * K_ + kc + tid];
        __syncthreads();

        u64 acc[4][8];
#pragma unroll
        for (int i = 0; i < 4; i++)
#pragma unroll
            for (int j = 0; j < 8; j++) acc[i][j] = 0ull;

#pragma unroll 2
        for (int d4 = 0; d4 < D_; d4 += 4) {
            u64 zp0[4], zp1[4];
#pragma unroll
            for (int i = 0; i < 4; i++) {
                ulonglong2 v = *(const ulonglong2*)(zbase + i * (16 * ZSTR) + d4);
                zp0[i] = v.x;   // (z[d4],   z[d4+1])
                zp1[i] = v.y;   // (z[d4+2], z[d4+3])
            }
#pragma unroll
            for (int j = 0; j < 8; j++) {
                u64 c0 = *(const u64*)(cbase + j * (16 * CSTR) + d4);
                u64 c1 = *(const u64*)(cbase + j * (16 * CSTR) + d4 + 2);
#pragma unroll
                for (int i = 0; i < 4; i++)
                    acc[i][j] = ffma2(zp0[i], c0, acc[i][j]);
#pragma unroll
                for (int i = 0; i < 4; i++)
                    acc[i][j] = ffma2(zp1[i], c1, acc[i][j]);
            }
        }

        // Emit dist + running argmin (k scanned ascending per thread)
#pragma unroll
        for (int i = 0; i < 4; i++) {
            int n = n0 + tn + 16 * i;
            float szi = sz[tn + 16 * i];
#pragma unroll
            for (int j = 0; j < 8; j++) {
                int kl = tk + 16 * j;
                int k  = kc + kl;
                float dot  = __fadd_rn(lo32(acc[i][j]), hi32(acc[i][j]));
                float szc  = __fadd_rn(szi, scs[kl]);          // fl(sz+sc), as ref
                float dist = __fmaf_rn(-2.f, dot, szc);        // fl(szc - 2*dot)
                prob[(size_t)n * 8192 + p * 2048 + k] = dist;
                if (dist < minv[i]) { minv[i] = dist; mink[i] = k; }
            }
        }
    }

    // Cross-thread argmin reduce: 16 lanes (same tn) are contiguous in a warp.
#pragma unroll
    for (int i = 0; i < 4; i++) {
        float bv = minv[i];
        int   bk = mink[i];
        for (int off = 8; off; off >>= 1) {
            float v2 = __shfl_down_sync(0xffffffffu, bv, off, 16);
            int   k2 = __shfl_down_sync(0xffffffffu, bk, off, 16);
            if (v2 < bv || (v2 == bv && k2 < bk)) { bv = v2; bk = k2; }
        }
        if (tk == 0) {
            int n = n0 + tn + 16 * i;
            g_minD[n * 4 + p] = bv;
            g_idx[n * 4 + p]  = bk;
        }
    }
}

// ---------------------------------------------------------------------------
// K2: in-place softmax normalize. One 64-thread group per row (4 rows/CTA).
__global__ void __launch_bounds__(256)
k_norm(float* __restrict__ out) {
    int g      = threadIdx.x >> 6;
    int lane64 = threadIdx.x & 63;
    int rho    = blockIdx.x * 4 + g;                 // rho = n*4 + p
    float* row = out + PROB_OFF + (size_t)rho * 2048;
    float m = g_minD[rho];

    float e[32];
    float s = 0.f;
#pragma unroll 4
    for (int ii = 0; ii < 32; ii++) {
        float dist = row[lane64 + 64 * ii];
        float ev = expf(2.f * (m - dist));
        e[ii] = ev;
        s += ev;
    }
    for (int o = 16; o; o >>= 1) s += __shfl_down_sync(0xffffffffu, s, o);
    __shared__ float wsum[8];
    if ((threadIdx.x & 31) == 0) wsum[threadIdx.x >> 5] = s;
    __syncthreads();
    float S = wsum[2 * g] + wsum[2 * g + 1];
    float inv = 1.0f / S;
#pragma unroll 4
    for (int ii = 0; ii < 32; ii++) row[lane64 + 64 * ii] = e[ii] * inv;
}

// ---------------------------------------------------------------------------
// K3: zq_out (straight-through, fl(zf + fl(zq - zf))) + per-CTA loss partials.
__global__ void __launch_bounds__(256)
k_zq(const float* __restrict__ z, const float* __restrict__ cb,
     float* __restrict__ out) {
    __shared__ float cz[TN][D_];
    __shared__ int   sidx[TN];
    __shared__ float lred[256];

    const int tile = blockIdx.x;
    const int p    = blockIdx.y;
    const int tid  = threadIdx.x;
    const int n0   = tile * TN;

    if (tid < TN) sidx[tid] = g_idx[(n0 + tid) * 4 + p];
    __syncthreads();

    for (int e = tid; e < TN * (D_ / 4); e += 256) {
        int r  = e >> 5;
        int j4 = e & 31;
        float4 v = *(const float4*)(cb + ((size_t)(p * K_ + sidx[r]) * D_) + j4 * 4);
        cz[r][j4 * 4 + 0] = v.x; cz[r][j4 * 4 + 1] = v.y;
        cz[r][j4 * 4 + 2] = v.z; cz[r][j4 * 4 + 3] = v.w;
    }
    __syncthreads();

    float ls = 0.f;
    for (int e = tid; e < TN * D_; e += 256) {
        int j = e >> 6;
        int r = e & 63;
        int n = n0 + r;
        int b = n / HW_;
        int hw = n - b * HW_;
        size_t ga = (size_t)(b * C_ + p * D_ + j) * HW_ + hw;
        float zf = z[ga];
        float d  = __fsub_rn(cz[r][j], zf);      // fl(zq - zf)
        out[ga]  = __fadd_rn(zf, d);             // zq_st
        ls = __fadd_rn(ls, __fmul_rn(d, d));
    }
    lred[tid] = ls;
    __syncthreads();
    for (int o = 128; o; o >>= 1) {
        if (tid < o) lred[tid] += lred[tid + o];
        __syncthreads();
    }
    if (tid == 0) g_losspart[p * NTILE + tile] = lred[0];
}

// ---------------------------------------------------------------------------
// K4: final deterministic loss reduction. q = m + fl(0.25*m).
__global__ void k_loss(float* __restrict__ out) {
    __shared__ float s[256];
    int tid = threadIdx.x;
    float a = 0.f;
    for (int e = tid; e < NTILE * P_; e += 256) a += g_losspart[e];
    s[tid] = a;
    __syncthreads();
    for (int o = 128; o; o >>= 1) {
        if (tid < o) s[tid] += s[tid + o];
        __syncthreads();
    }
    if (tid == 0) {
        float m = s[0] / 6422528.0f;
        out[LOSS_OFF] = __fadd_rn(m, __fmul_rn(0.25f, m));
    }
}

// ---------------------------------------------------------------------------
extern "C" void kernel_launch(void* const* d_in, const int* in_sizes, int n_in,
                              void* d_out, int out_size) {
    const float* z  = (const float*)d_in[0];   // [16,512,28,28]
    const float* cb = (const float*)d_in[1];   // [4,2048,128]
    float* out = (float*)d_out;

    const int smem_k1 = (TN * ZSTR + TKC * CSTR + TN + TKC) * (int)sizeof(float);
    cudaFuncSetAttribute(k_main, cudaFuncAttributeMaxDynamicSharedMemorySize, smem_k1);

    k_sc<<<32, 256>>>(cb);
    k_main<<<dim3(NTILE, P_), 256, smem_k1>>>(z, cb, out);
    k_norm<<<N_, 256>>>(out);
    k_zq<<<dim3(NTILE, P_), 256>>>(z, cb, out);
    k_loss<<<1, 256>>>(out);
}

// round 5
// speedup vs baseline: 1.5596x; 1.0018x over previous
#include <cuda_runtime.h>

// Problem constants
#define B_    16
#define C_    512
#define HW_   784          // 28*28
#define P_    4
#define K_    2048
#define D_    128
#define N_    12544        // B_*HW_
#define NP_   50176        // N_*P_
#define TN    64           // n-rows per CTA tile (12544 = 196*64)
#define TKC   128          // k-chunk
#define NTILE 196

#define ZSTR  132          // z smem row stride (floats), 16B-aligned rows
#define CSTR  130          // c smem row stride (floats), conflict-free LDS.64

// d_out layout: [zq_out (6422528 f32)] [q_loss (1 f32)] [distance_prob (N_*P_*K_ f32)]
#define LOSS_OFF 6422528
#define PROB_OFF 6422529

typedef unsigned long long u64;

__device__ __forceinline__ u64 ffma2(u64 a, u64 b, u64 c) {
    u64 d;
    asm("fma.rn.f32x2 %0, %1, %2, %3;" : "=l"(d) : "l"(a), "l"(b), "l"(c));
    return d;
}
__device__ __forceinline__ float lo32(u64 v) { return __uint_as_float((unsigned)(v & 0xffffffffull)); }
__device__ __forceinline__ float hi32(u64 v) { return __uint_as_float((unsigned)(v >> 32)); }

// Scratch (no allocations allowed)
__device__ float g_sc[P_ * K_];        // ||codebook row||^2
__device__ float g_minD[NP_];          // per (n*4+p) min dist
__device__ int   g_idx[NP_];           // per (n*4+p) argmin k
__device__ float g_losspart[NTILE * P_];

// ---------------------------------------------------------------------------
// K0: per-codeword squared norm, sequential fp32 sum (mul then add, matching
// reference's separate square+reduce structure).
__global__ void k_sc(const float* __restrict__ cb) {
    int t = blockIdx.x * 256 + threadIdx.x;        // 0..8191 = p*K_+k
    const float* row = cb + (size_t)t * D_;
    float s = 0.f;
    for (int j = 0; j < D_; j++) {
        float q = __fmul_rn(row[j], row[j]);
        s = __fadd_rn(s, q);
    }
    g_sc[t] = s;
}

// ---------------------------------------------------------------------------
// K1: main GEMM pass with packed FFMA2 (fma.rn.f32x2).
// Accumulators are packed over d-parity: acc = (sum over even-pair d's,
// sum over odd-pair d's); dot = lo+hi. Both operands are natural
// consecutive-d pairs -> no transpose/duplication needed in smem.
// Grid (196, 4), 256 threads = 16(tk) x 16(tn). Per-thread microtile:
// 4 n-rows x 8 k's. Writes raw dist into prob region, tracks argmin.
__global__ void __launch_bounds__(256, 2)
k_main(const float* __restrict__ z, const float* __restrict__ cb,
       float* __restrict__ out) {
    extern __shared__ float sm[];
    float* zs  = sm;                        // [TN][ZSTR]
    float* cs  = zs + TN * ZSTR;            // [TKC][CSTR]
    float* sz  = cs + TKC * CSTR;           // [TN]
    float* scs = sz + TN;                   // [TKC]

    const int tile = blockIdx.x;
    const int p    = blockIdx.y;
    const int tid  = threadIdx.x;
    const int n0   = tile * TN;

    // Load z tile: zs[r][j] = z[b, p*128+j, hw], coalesced over r.
    for (int e = tid; e < TN * D_; e += 256) {
        int j = e >> 6;            // e / 64
        int r = e & 63;
        int n = n0 + r;
        int b = n / HW_;
        int hw = n - b * HW_;
        zs[r * ZSTR + j] = z[(size_t)(b * C_ + p * D_ + j) * HW_ + hw];
    }
    __syncthreads();

    // sz[r] = sequential fp32 sum of squares (mul+add, matching ref structure)
    if (tid < TN) {
        const float* zr = zs + tid * ZSTR;
        float s = 0.f;
        for (int j = 0; j < D_; j++) {
            float q = __fmul_rn(zr[j], zr[j]);
            s = __fadd_rn(s, q);
        }
        sz[tid] = s;
    }

    const int tk = tid & 15;
    const int tn = tid >> 4;

    float minv[4];
    int   mink[4];
#pragma unroll
    for (int i = 0; i < 4; i++) { minv[i] = 3.4e38f; mink[i] = 0; }

    float* prob = out + PROB_OFF;

    const float* zbase = zs + tn * ZSTR;   // rows tn + 16*i
    const float* cbase = cs + tk * CSTR;   // k = tk + 16*j

    for (int kc = 0; kc < K_; kc += TKC) {
        __syncthreads();   // protect cs/scs reuse + sz visibility
        // Load codebook chunk (coalesced float4 over d)
        for (int e = tid; e < TKC * (D_ / 4); e += 256) {
            int kr = e >> 5;
            int j4 = e & 31;
            float4 v = *(const float4*)(cb + ((size_t)(p * K_ + kc + kr) * D_) + j4 * 4);
            float* dst = cs + kr * CSTR + j4 * 4;
            dst[0] = v.x; dst[1] = v.y; dst[2] = v.z; dst[3] = v.w;
        }
        if (tid < TKC) scs[tid] = g_sc[p * K_ + kc + tid];
        __syncthreads();

        u64 acc[4][8];
#pragma unroll
        for (int i = 0; i < 4; i++)
#pragma unroll
            for (int j = 0; j < 8; j++) acc[i][j] = 0ull;

#pragma unroll 2
        for (int d4 = 0; d4 < D_; d4 += 4) {
            u64 zp0[4], zp1[4];
#pragma unroll
            for (int i = 0; i < 4; i++) {
                ulonglong2 v = *(const ulonglong2*)(zbase + i * (16 * ZSTR) + d4);
                zp0[i] = v.x;   // (z[d4],   z[d4+1])
                zp1[i] = v.y;   // (z[d4+2], z[d4+3])
            }
#pragma unroll
            for (int j = 0; j < 8; j++) {
                u64 c0 = *(const u64*)(cbase + j * (16 * CSTR) + d4);
                u64 c1 = *(const u64*)(cbase + j * (16 * CSTR) + d4 + 2);
#pragma unroll
                for (int i = 0; i < 4; i++)
                    acc[i][j] = ffma2(zp0[i], c0, acc[i][j]);
#pragma unroll
                for (int i = 0; i < 4; i++)
                    acc[i][j] = ffma2(zp1[i], c1, acc[i][j]);
            }
        }

        // Emit dist + running argmin (k scanned ascending per thread)
#pragma unroll
        for (int i = 0; i < 4; i++) {
            int n = n0 + tn + 16 * i;
            float szi = sz[tn + 16 * i];
#pragma unroll
            for (int j = 0; j < 8; j++) {
                int kl = tk + 16 * j;
                int k  = kc + kl;
                float dot  = __fadd_rn(lo32(acc[i][j]), hi32(acc[i][j]));
                float szc  = __fadd_rn(szi, scs[kl]);          // fl(sz+sc), as ref
                float dist = __fmaf_rn(-2.f, dot, szc);        // fl(szc - 2*dot)
                prob[(size_t)n * 8192 + p * 2048 + k] = dist;
                if (dist < minv[i]) { minv[i] = dist; mink[i] = k; }
            }
        }
    }

    // Cross-thread argmin reduce: 16 lanes (same tn) are contiguous in a warp.
#pragma unroll
    for (int i = 0; i < 4; i++) {
        float bv = minv[i];
        int   bk = mink[i];
        for (int off = 8; off; off >>= 1) {
            float v2 = __shfl_down_sync(0xffffffffu, bv, off, 16);
            int   k2 = __shfl_down_sync(0xffffffffu, bk, off, 16);
            if (v2 < bv || (v2 == bv && k2 < bk)) { bv = v2; bk = k2; }
        }
        if (tk == 0) {
            int n = n0 + tn + 16 * i;
            g_minD[n * 4 + p] = bv;
            g_idx[n * 4 + p]  = bk;
        }
    }
}

// ---------------------------------------------------------------------------
// K2: in-place softmax normalize. One 64-thread group per row (4 rows/CTA).
__global__ void __launch_bounds__(256)
k_norm(float* __restrict__ out) {
    int g      = threadIdx.x >> 6;
    int lane64 = threadIdx.x & 63;
    int rho    = blockIdx.x * 4 + g;                 // rho = n*4 + p
    float* row = out + PROB_OFF + (size_t)rho * 2048;
    float m = g_minD[rho];

    float e[32];
    float s = 0.f;
#pragma unroll 4
    for (int ii = 0; ii < 32; ii++) {
        float dist = row[lane64 + 64 * ii];
        float ev = expf(2.f * (m - dist));
        e[ii] = ev;
        s += ev;
    }
    for (int o = 16; o; o >>= 1) s += __shfl_down_sync(0xffffffffu, s, o);
    __shared__ float wsum[8];
    if ((threadIdx.x & 31) == 0) wsum[threadIdx.x >> 5] = s;
    __syncthreads();
    float S = wsum[2 * g] + wsum[2 * g + 1];
    float inv = 1.0f / S;
#pragma unroll 4
    for (int ii = 0; ii < 32; ii++) row[lane64 + 64 * ii] = e[ii] * inv;
}

// ---------------------------------------------------------------------------
// K3: zq_out (straight-through, fl(zf + fl(zq - zf))) + per-CTA loss partials.
__global__ void __launch_bounds__(256)
k_zq(const float* __restrict__ z, const float* __restrict__ cb,
     float* __restrict__ out) {
    __shared__ float cz[TN][D_];
    __shared__ int   sidx[TN];
    __shared__ float lred[256];

    const int tile = blockIdx.x;
    const int p    = blockIdx.y;
    const int tid  = threadIdx.x;
    const int n0   = tile * TN;

    if (tid < TN) sidx[tid] = g_idx[(n0 + tid) * 4 + p];
    __syncthreads();

    for (int e = tid; e < TN * (D_ / 4); e += 256) {
        int r  = e >> 5;
        int j4 = e & 31;
        float4 v = *(const float4*)(cb + ((size_t)(p * K_ + sidx[r]) * D_) + j4 * 4);
        cz[r][j4 * 4 + 0] = v.x; cz[r][j4 * 4 + 1] = v.y;
        cz[r][j4 * 4 + 2] = v.z; cz[r][j4 * 4 + 3] = v.w;
    }
    __syncthreads();

    float ls = 0.f;
    for (int e = tid; e < TN * D_; e += 256) {
        int j = e >> 6;
        int r = e & 63;
        int n = n0 + r;
        int b = n / HW_;
        int hw = n - b * HW_;
        size_t ga = (size_t)(b * C_ + p * D_ + j) * HW_ + hw;
        float zf = z[ga];
        float d  = __fsub_rn(cz[r][j], zf);      // fl(zq - zf)
        out[ga]  = __fadd_rn(zf, d);             // zq_st
        ls = __fadd_rn(ls, __fmul_rn(d, d));
    }
    lred[tid] = ls;
    __syncthreads();
    for (int o = 128; o; o >>= 1) {
        if (tid < o) lred[tid] += lred[tid + o];
        __syncthreads();
    }
    if (tid == 0) g_losspart[p * NTILE + tile] = lred[0];
}

// ---------------------------------------------------------------------------
// K4: final deterministic loss reduction. q = m + fl(0.25*m).
__global__ void k_loss(float* __restrict__ out) {
    __shared__ float s[256];
    int tid = threadIdx.x;
    float a = 0.f;
    for (int e = tid; e < NTILE * P_; e += 256) a += g_losspart[e];
    s[tid] = a;
    __syncthreads();
    for (int o = 128; o; o >>= 1) {
        if (tid < o) s[tid] += s[tid + o];
        __syncthreads();
    }
    if (tid == 0) {
        float m = s[0] / 6422528.0f;
        out[LOSS_OFF] = __fadd_rn(m, __fmul_rn(0.25f, m));
    }
}

// ---------------------------------------------------------------------------
extern "C" void kernel_launch(void* const* d_in, const int* in_sizes, int n_in,
                              void* d_out, int out_size) {
    const float* z  = (const float*)d_in[0];   // [16,512,28,28]
    const float* cb = (const float*)d_in[1];   // [4,2048,128]
    float* out = (float*)d_out;

    const int smem_k1 = (TN * ZSTR + TKC * CSTR + TN + TKC) * (int)sizeof(float);
    cudaFuncSetAttribute(k_main, cudaFuncAttributeMaxDynamicSharedMemorySize, smem_k1);

    k_sc<<<32, 256>>>(cb);
    k_main<<<dim3(NTILE, P_), 256, smem_k1>>>(z, cb, out);
    k_norm<<<N_, 256>>>(out);
    k_zq<<<dim3(NTILE, P_), 256>>>(z, cb, out);
    k_loss<<<1, 256>>>(out);
}

// round 6
// speedup vs baseline: 1.5600x; 1.0002x over previous
#include <cuda_runtime.h>

// Problem constants
#define B_    16
#define C_    512
#define HW_   784          // 28*28
#define P_    4
#define K_    2048
#define D_    128
#define N_    12544        // B_*HW_
#define NP_   50176        // N_*P_
#define TN    64           // n-rows per CTA tile (12544 = 196*64)
#define TKC   128          // k-chunk
#define NTILE 196

#define ZSTR  132          // z smem row stride (floats), 16B-aligned rows
#define CSTR  130          // c smem row stride (floats), conflict-free LDS.64

// d_out layout: [zq_out (6422528 f32)] [q_loss (1 f32)] [distance_prob (N_*P_*K_ f32)]
#define LOSS_OFF 6422528
#define PROB_OFF 6422529

typedef unsigned long long u64;

__device__ __forceinline__ u64 ffma2(u64 a, u64 b, u64 c) {
    u64 d;
    asm("fma.rn.f32x2 %0, %1, %2, %3;" : "=l"(d) : "l"(a), "l"(b), "l"(c));
    return d;
}
__device__ __forceinline__ float lo32(u64 v) { return __uint_as_float((unsigned)(v & 0xffffffffull)); }
__device__ __forceinline__ float hi32(u64 v) { return __uint_as_float((unsigned)(v >> 32)); }

// Scratch (no allocations allowed)
__device__ float g_sc[P_ * K_];        // ||codebook row||^2
__device__ float g_minD[NP_];          // per (n*4+p) min dist
__device__ int   g_idx[NP_];           // per (n*4+p) argmin k
__device__ float g_losspart[NTILE * P_];

// ---------------------------------------------------------------------------
// K0: per-codeword squared norm, sequential fp32 sum (mul then add, matching
// reference's separate square+reduce structure).
__global__ void k_sc(const float* __restrict__ cb) {
    int t = blockIdx.x * 256 + threadIdx.x;        // 0..8191 = p*K_+k
    const float* row = cb + (size_t)t * D_;
    float s = 0.f;
    for (int j = 0; j < D_; j++) {
        float q = __fmul_rn(row[j], row[j]);
        s = __fadd_rn(s, q);
    }
    g_sc[t] = s;
}

// ---------------------------------------------------------------------------
// K1: main GEMM pass with packed FFMA2 (fma.rn.f32x2).
// Accumulators are packed over d-parity: acc = (sum over even-pair d's,
// sum over odd-pair d's); dot = lo+hi. Both operands are natural
// consecutive-d pairs -> no transpose/duplication needed in smem.
// Grid (196, 4), 256 threads = 16(tk) x 16(tn). Per-thread microtile:
// 4 n-rows x 8 k's. Writes raw dist into prob region, tracks argmin.
__global__ void __launch_bounds__(256, 2)
k_main(const float* __restrict__ z, const float* __restrict__ cb,
       float* __restrict__ out) {
    extern __shared__ float sm[];
    float* zs  = sm;                        // [TN][ZSTR]
    float* cs  = zs + TN * ZSTR;            // [TKC][CSTR]
    float* sz  = cs + TKC * CSTR;           // [TN]
    float* scs = sz + TN;                   // [TKC]

    const int tile = blockIdx.x;
    const int p    = blockIdx.y;
    const int tid  = threadIdx.x;
    const int n0   = tile * TN;

    // Load z tile: zs[r][j] = z[b, p*128+j, hw], coalesced over r.
    for (int e = tid; e < TN * D_; e += 256) {
        int j = e >> 6;            // e / 64
        int r = e & 63;
        int n = n0 + r;
        int b = n / HW_;
        int hw = n - b * HW_;
        zs[r * ZSTR + j] = z[(size_t)(b * C_ + p * D_ + j) * HW_ + hw];
    }
    __syncthreads();

    // sz[r] = sequential fp32 sum of squares (mul+add, matching ref structure)
    if (tid < TN) {
        const float* zr = zs + tid * ZSTR;
        float s = 0.f;
        for (int j = 0; j < D_; j++) {
            float q = __fmul_rn(zr[j], zr[j]);
            s = __fadd_rn(s, q);
        }
        sz[tid] = s;
    }

    const int tk = tid & 15;
    const int tn = tid >> 4;

    float minv[4];
    int   mink[4];
#pragma unroll
    for (int i = 0; i < 4; i++) { minv[i] = 3.4e38f; mink[i] = 0; }

    float* prob = out + PROB_OFF;

    const float* zbase = zs + tn * ZSTR;   // rows tn + 16*i
    const float* cbase = cs + tk * CSTR;   // k = tk + 16*j

    for (int kc = 0; kc < K_; kc += TKC) {
        __syncthreads();   // protect cs/scs reuse + sz visibility
        // Load codebook chunk (coalesced float4 over d)
        for (int e = tid; e < TKC * (D_ / 4); e += 256) {
            int kr = e >> 5;
            int j4 = e & 31;
            float4 v = *(const float4*)(cb + ((size_t)(p * K_ + kc + kr) * D_) + j4 * 4);
            float* dst = cs + kr * CSTR + j4 * 4;
            dst[0] = v.x; dst[1] = v.y; dst[2] = v.z; dst[3] = v.w;
        }
        if (tid < TKC) scs[tid] = g_sc[p * K_ + kc + tid];
        __syncthreads();

        u64 acc[4][8];
#pragma unroll
        for (int i = 0; i < 4; i++)
#pragma unroll
            for (int j = 0; j < 8; j++) acc[i][j] = 0ull;

#pragma unroll 2
        for (int d4 = 0; d4 < D_; d4 += 4) {
            u64 zp0[4], zp1[4];
#pragma unroll
            for (int i = 0; i < 4; i++) {
                ulonglong2 v = *(const ulonglong2*)(zbase + i * (16 * ZSTR) + d4);
                zp0[i] = v.x;   // (z[d4],   z[d4+1])
                zp1[i] = v.y;   // (z[d4+2], z[d4+3])
            }
#pragma unroll
            for (int j = 0; j < 8; j++) {
                u64 c0 = *(const u64*)(cbase + j * (16 * CSTR) + d4);
                u64 c1 = *(const u64*)(cbase + j * (16 * CSTR) + d4 + 2);
#pragma unroll
                for (int i = 0; i < 4; i++)
                    acc[i][j] = ffma2(zp0[i], c0, acc[i][j]);
#pragma unroll
                for (int i = 0; i < 4; i++)
                    acc[i][j] = ffma2(zp1[i], c1, acc[i][j]);
            }
        }

        // Emit dist + running argmin (k scanned ascending per thread)
#pragma unroll
        for (int i = 0; i < 4; i++) {
            int n = n0 + tn + 16 * i;
            float szi = sz[tn + 16 * i];
#pragma unroll
            for (int j = 0; j < 8; j++) {
                int kl = tk + 16 * j;
                int k  = kc + kl;
                float dot  = __fadd_rn(lo32(acc[i][j]), hi32(acc[i][j]));
                float szc  = __fadd_rn(szi, scs[kl]);          // fl(sz+sc), as ref
                float dist = __fmaf_rn(-2.f, dot, szc);        // fl(szc - 2*dot)
                prob[(size_t)n * 8192 + p * 2048 + k] = dist;
                if (dist < minv[i]) { minv[i] = dist; mink[i] = k; }
            }
        }
    }

    // Cross-thread argmin reduce: 16 lanes (same tn) are contiguous in a warp.
#pragma unroll
    for (int i = 0; i < 4; i++) {
        float bv = minv[i];
        int   bk = mink[i];
        for (int off = 8; off; off >>= 1) {
            float v2 = __shfl_down_sync(0xffffffffu, bv, off, 16);
            int   k2 = __shfl_down_sync(0xffffffffu, bk, off, 16);
            if (v2 < bv || (v2 == bv && k2 < bk)) { bv = v2; bk = k2; }
        }
        if (tk == 0) {
            int n = n0 + tn + 16 * i;
            g_minD[n * 4 + p] = bv;
            g_idx[n * 4 + p]  = bk;
        }
    }
}

// ---------------------------------------------------------------------------
// K2: in-place softmax normalize. One 64-thread group per row (4 rows/CTA).
__global__ void __launch_bounds__(256)
k_norm(float* __restrict__ out) {
    int g      = threadIdx.x >> 6;
    int lane64 = threadIdx.x & 63;
    int rho    = blockIdx.x * 4 + g;                 // rho = n*4 + p
    float* row = out + PROB_OFF + (size_t)rho * 2048;
    float m = g_minD[rho];

    float e[32];
    float s = 0.f;
#pragma unroll 4
    for (int ii = 0; ii < 32; ii++) {
        float dist = row[lane64 + 64 * ii];
        float ev = expf(2.f * (m - dist));
        e[ii] = ev;
        s += ev;
    }
    for (int o = 16; o; o >>= 1) s += __shfl_down_sync(0xffffffffu, s, o);
    __shared__ float wsum[8];
    if ((threadIdx.x & 31) == 0) wsum[threadIdx.x >> 5] = s;
    __syncthreads();
    float S = wsum[2 * g] + wsum[2 * g + 1];
    float inv = 1.0f / S;
#pragma unroll 4
    for (int ii = 0; ii < 32; ii++) row[lane64 + 64 * ii] = e[ii] * inv;
}

// ---------------------------------------------------------------------------
// K3: zq_out (straight-through, fl(zf + fl(zq - zf))) + per-CTA loss partials.
__global__ void __launch_bounds__(256)
k_zq(const float* __restrict__ z, const float* __restrict__ cb,
     float* __restrict__ out) {
    __shared__ float cz[TN][D_];
    __shared__ int   sidx[TN];
    __shared__ float lred[256];

    const int tile = blockIdx.x;
    const int p    = blockIdx.y;
    const int tid  = threadIdx.x;
    const int n0   = tile * TN;

    if (tid < TN) sidx[tid] = g_idx[(n0 + tid) * 4 + p];
    __syncthreads();

    for (int e = tid; e < TN * (D_ / 4); e += 256) {
        int r  = e >> 5;
        int j4 = e & 31;
        float4 v = *(const float4*)(cb + ((size_t)(p * K_ + sidx[r]) * D_) + j4 * 4);
        cz[r][j4 * 4 + 0] = v.x; cz[r][j4 * 4 + 1] = v.y;
        cz[r][j4 * 4 + 2] = v.z; cz[r][j4 * 4 + 3] = v.w;
    }
    __syncthreads();

    float ls = 0.f;
    for (int e = tid; e < TN * D_; e += 256) {
        int j = e >> 6;
        int r = e & 63;
        int n = n0 + r;
        int b = n / HW_;
        int hw = n - b * HW_;
        size_t ga = (size_t)(b * C_ + p * D_ + j) * HW_ + hw;
        float zf = z[ga];
        float d  = __fsub_rn(cz[r][j], zf);      // fl(zq - zf)
        out[ga]  = __fadd_rn(zf, d);             // zq_st
        ls = __fadd_rn(ls, __fmul_rn(d, d));
    }
    lred[tid] = ls;
    __syncthreads();
    for (int o = 128; o; o >>= 1) {
        if (tid < o) lred[tid] += lred[tid + o];
        __syncthreads();
    }
    if (tid == 0) g_losspart[p * NTILE + tile] = lred[0];
}

// ---------------------------------------------------------------------------
// K4: final deterministic loss reduction. q = m + fl(0.25*m).
__global__ void k_loss(float* __restrict__ out) {
    __shared__ float s[256];
    int tid = threadIdx.x;
    float a = 0.f;
    for (int e = tid; e < NTILE * P_; e += 256) a += g_losspart[e];
    s[tid] = a;
    __syncthreads();
    for (int o = 128; o; o >>= 1) {
        if (tid < o) s[tid] += s[tid + o];
        __syncthreads();
    }
    if (tid == 0) {
        float m = s[0] / 6422528.0f;
        out[LOSS_OFF] = __fadd_rn(m, __fmul_rn(0.25f, m));
    }
}

// ---------------------------------------------------------------------------
extern "C" void kernel_launch(void* const* d_in, const int* in_sizes, int n_in,
                              void* d_out, int out_size) {
    const float* z  = (const float*)d_in[0];   // [16,512,28,28]
    const float* cb = (const float*)d_in[1];   // [4,2048,128]
    float* out = (float*)d_out;

    const int smem_k1 = (TN * ZSTR + TKC * CSTR + TN + TKC) * (int)sizeof(float);
    cudaFuncSetAttribute(k_main, cudaFuncAttributeMaxDynamicSharedMemorySize, smem_k1);

    k_sc<<<32, 256>>>(cb);
    k_main<<<dim3(NTILE, P_), 256, smem_k1>>>(z, cb, out);
    k_norm<<<N_, 256>>>(out);
    k_zq<<<dim3(NTILE, P_), 256>>>(z, cb, out);
    k_loss<<<1, 256>>>(out);
}

// round 9
// speedup vs baseline: 2.3366x; 1.4979x over previous
#include <cuda_runtime.h>
#include <cstdint>
#include <cfloat>

// Problem constants
#define B_    16
#define C_    512
#define HW_   784          // 28*28
#define P_    4
#define K_    2048
#define D_    128
#define N_    12544        // B_*HW_
#define NP_   50176        // N_*P_
#define MT    128          // m-rows per CTA in k_mma
#define MTILE 98           // 12544 / 128
#define TKC   64           // codes per chunk
#define NCHUNK 32          // 2048/64
#define TN    64           // k_zq tile
#define NTILE 196

// d_out layout: [zq_out (6422528 f32)] [q_loss (1 f32)] [distance_prob (N_*P_*K_ f32)]
#define LOSS_OFF 6422528
#define PROB_OFF 6422529   // NOTE: odd -> prob base is only 4-byte aligned.
                           // All prob accesses MUST be scalar float.

#define EPS_RESCUE 1e-4f

// smem float offsets for k_mma
#define OFF_A    0                      // [128][132] tf32 bits
#define OFF_B    (128 * 132)            // [64][132] tf32 bits
#define OFF_SSZ  (OFF_B + 64 * 132)     // [128]
#define OFF_SM1  (OFF_SSZ + 128)        // [256]
#define OFF_SK1  (OFF_SM1 + 256)
#define OFF_SM2  (OFF_SK1 + 256)
#define OFF_SK2  (OFF_SM2 + 256)
#define SMEM_FLOATS (OFF_SK2 + 256)     // 26496 floats = 105984 B

// Scratch (no allocations allowed)
__device__ float g_sc[P_ * K_];        // ||codebook row||^2 (exact fp32, ref order)
__device__ float g_minD[NP_];          // per (n*4+p) min dist (tf32-based)
__device__ int   g_idx[NP_];           // per (n*4+p) argmin k
__device__ float g_m2[NP_];            // runner-up dist
__device__ int   g_k2[NP_];            // runner-up index
__device__ float g_szv[NP_];           // exact sz per (n,p), ref order
__device__ float g_losspart[NTILE * P_];

__device__ __forceinline__ uint32_t f2tf32(float f) {
    uint32_t r;
    asm("cvt.rna.tf32.f32 %0, %1;" : "=r"(r) : "f"(f));
    return r;
}

__device__ __forceinline__ void mma_tf32(float acc[4], const uint32_t a[4],
                                         uint32_t b0, uint32_t b1) {
    asm volatile(
        "mma.sync.aligned.m16n8k8.row.col.f32.tf32.tf32.f32 "
        "{%0,%1,%2,%3},{%4,%5,%6,%7},{%8,%9},{%0,%1,%2,%3};"
        : "+f"(acc[0]), "+f"(acc[1]), "+f"(acc[2]), "+f"(acc[3])
        : "r"(a[0]), "r"(a[1]), "r"(a[2]), "r"(a[3]), "r"(b0), "r"(b1));
}

__device__ __forceinline__ bool better(float v, int k, float m, int km) {
    return v < m || (v == m && k < km);
}
// merge top-2 (b1,b2 sorted) into (a1,a2 sorted)
__device__ __forceinline__ void merge2(float& a1, int& ka1, float& a2, int& ka2,
                                       float b1, int kb1, float b2, int kb2) {
    if (better(b1, kb1, a1, ka1)) {
        float t1 = a1; int tk1 = ka1;
        a1 = b1; ka1 = kb1;
        if (better(t1, tk1, b2, kb2)) { a2 = t1; ka2 = tk1; }
        else                          { a2 = b2; ka2 = kb2; }
    } else if (better(b1, kb1, a2, ka2)) {
        a2 = b1; ka2 = kb1;
    }
}

// ---------------------------------------------------------------------------
// K0: per-codeword squared norm (exact fp32, sequential ref order)
__global__ void k_sc(const float* __restrict__ cb) {
    int t = blockIdx.x * 256 + threadIdx.x;
    const float* row = cb + (size_t)t * D_;
    float s = 0.f;
    for (int j = 0; j < D_; j++) {
        float q = __fmul_rn(row[j], row[j]);
        s = __fadd_rn(s, q);
    }
    g_sc[t] = s;
}

// ---------------------------------------------------------------------------
// K1: tf32 mma.sync GEMM. Grid (98, 4), 256 threads, 2 CTAs/SM.
// Writes raw dist to prob region (scalar stores only — prob base is odd);
// tracks per-row top-2 for the exact rescue.
__global__ void __launch_bounds__(256, 2)
k_mma(const float* __restrict__ z, const float* __restrict__ cb,
      float* __restrict__ out) {
    extern __shared__ float sm[];
    uint32_t* sAu = (uint32_t*)(sm + OFF_A);
    uint32_t* sBu = (uint32_t*)(sm + OFF_B);
    float*    ssz = sm + OFF_SSZ;
    float*    sm1 = sm + OFF_SM1;
    int*      sk1 = (int*)(sm + OFF_SK1);
    float*    sm2 = sm + OFF_SM2;
    int*      sk2 = (int*)(sm + OFF_SK2);

    const int tid  = threadIdx.x;
    const int lane = tid & 31;
    const int wid  = tid >> 5;
    const int p    = blockIdx.y;
    const int n0   = blockIdx.x * MT;
    const int g    = lane >> 2;      // 0..7
    const int tig  = lane & 3;       // 0..3
    const int mw   = (wid & 3) * 32; // warp m offset
    const int kw   = (wid >> 2) * 32;// warp k offset within chunk

    // A tile load + tf32 convert (each thread: one row, every other j)
    {
        int r = tid & 127, j0 = tid >> 7;
        int n = n0 + r, b = n / HW_, hw = n - b * HW_;
        const float* zr = z + (size_t)(b * C_ + p * D_) * HW_ + hw;
#pragma unroll 4
        for (int i = 0; i < 64; i++) {
            int j = j0 + 2 * i;
            sAu[r * 132 + j] = f2tf32(zr[(size_t)j * HW_]);
        }
    }
    // exact sz, strict sequential order (matches reference reduction order)
    if (tid < 128) {
        int r = tid, n = n0 + r, b = n / HW_, hw = n - b * HW_;
        const float* zr = z + (size_t)(b * C_ + p * D_) * HW_ + hw;
        float s = 0.f;
        for (int j = 0; j < D_; j++) {
            float v = zr[(size_t)j * HW_];
            s = __fadd_rn(s, __fmul_rn(v, v));
        }
        ssz[r] = s;
        g_szv[(size_t)(n0 + r) * 4 + p] = s;
    }
    __syncthreads();

    // per-thread row sz cache (rows: mw + 16*im + 8*rr + g, t = 2*im+rr)
    float szr[4];
#pragma unroll
    for (int t = 0; t < 4; t++)
        szr[t] = ssz[mw + 16 * (t >> 1) + 8 * (t & 1) + g];

    float m1v[4], m2v[4];
    int   k1v[4], k2v[4];
#pragma unroll
    for (int t = 0; t < 4; t++) {
        m1v[t] = FLT_MAX; m2v[t] = FLT_MAX; k1v[t] = 0; k2v[t] = 0;
    }

    float* prob = out + PROB_OFF;
    const float* scg = g_sc + p * K_;

    for (int c = 0; c < NCHUNK; c++) {
        __syncthreads();   // prior chunk's mma reads of sB complete
        // B chunk load + tf32 convert (coalesced float4)
        {
            const float* src = cb + ((size_t)(p * K_ + c * TKC)) * D_;
            for (int e = tid; e < TKC * 32; e += 256) {
                int kr = e >> 5, j4 = e & 31;
                float4 v = *(const float4*)(src + (size_t)kr * D_ + j4 * 4);
                uint4 t;
                t.x = f2tf32(v.x); t.y = f2tf32(v.y);
                t.z = f2tf32(v.z); t.w = f2tf32(v.w);
                *(uint4*)&sBu[kr * 132 + j4 * 4] = t;
            }
        }
        __syncthreads();

        float acc[2][4][4];
#pragma unroll
        for (int im = 0; im < 2; im++)
#pragma unroll
            for (int j = 0; j < 4; j++)
#pragma unroll
                for (int q = 0; q < 4; q++) acc[im][j][q] = 0.f;

#pragma unroll
        for (int s = 0; s < 16; s++) {
            const int d0 = 8 * s;
            uint32_t af[2][4];
#pragma unroll
            for (int im = 0; im < 2; im++) {
                int base = (mw + 16 * im + g) * 132 + d0 + tig;
                af[im][0] = sAu[base];
                af[im][1] = sAu[base + 8 * 132];
                af[im][2] = sAu[base + 4];
                af[im][3] = sAu[base + 8 * 132 + 4];
            }
#pragma unroll
            for (int j = 0; j < 4; j++) {
                int nb = kw + 8 * j + g;
                uint32_t b0 = sBu[nb * 132 + d0 + tig];
                uint32_t b1 = sBu[nb * 132 + d0 + tig + 4];
                mma_tf32(acc[0][j], af[0], b0, b1);
                mma_tf32(acc[1][j], af[1], b0, b1);
            }
        }

        // epilogue: dist, scalar streaming stores (prob base is odd-aligned),
        // top-2 update
        const int kc = c * TKC + kw;
#pragma unroll
        for (int im = 0; im < 2; im++) {
#pragma unroll
            for (int rr = 0; rr < 2; rr++) {
                const int t = 2 * im + rr;
                const float sz_ = szr[t];
                const int rowg = n0 + mw + 16 * im + 8 * rr + g;
                float* prow = prob + (size_t)rowg * 8192 + p * 2048;
#pragma unroll
                for (int j = 0; j < 4; j++) {
                    int k = kc + 8 * j + 2 * tig;
                    float sc0 = __ldg(scg + k);
                    float sc1 = __ldg(scg + k + 1);
                    float d0v = __fmaf_rn(-2.f, acc[im][j][2 * rr],
                                          __fadd_rn(sz_, sc0));
                    float d1v = __fmaf_rn(-2.f, acc[im][j][2 * rr + 1],
                                          __fadd_rn(sz_, sc1));
                    __stcs(prow + k,     d0v);
                    __stcs(prow + k + 1, d1v);
                    if (better(d0v, k, m1v[t], k1v[t])) {
                        m2v[t] = m1v[t]; k2v[t] = k1v[t];
                        m1v[t] = d0v;    k1v[t] = k;
                    } else if (better(d0v, k, m2v[t], k2v[t])) {
                        m2v[t] = d0v; k2v[t] = k;
                    }
                    if (better(d1v, k + 1, m1v[t], k1v[t])) {
                        m2v[t] = m1v[t]; k2v[t] = k1v[t];
                        m1v[t] = d1v;    k1v[t] = k + 1;
                    } else if (better(d1v, k + 1, m2v[t], k2v[t])) {
                        m2v[t] = d1v; k2v[t] = k + 1;
                    }
                }
            }
        }
    }

    // quad merge (lanes sharing the same rows: same g, tig 0..3)
#pragma unroll
    for (int t = 0; t < 4; t++) {
#pragma unroll
        for (int off = 1; off <= 2; off <<= 1) {
            float o1 = __shfl_xor_sync(0xffffffffu, m1v[t], off);
            int  ok1 = __shfl_xor_sync(0xffffffffu, k1v[t], off);
            float o2 = __shfl_xor_sync(0xffffffffu, m2v[t], off);
            int  ok2 = __shfl_xor_sync(0xffffffffu, k2v[t], off);
            merge2(m1v[t], k1v[t], m2v[t], k2v[t], o1, ok1, o2, ok2);
        }
    }
    __syncthreads();
    if (tig == 0) {
        int kg = wid >> 2;
#pragma unroll
        for (int t = 0; t < 4; t++) {
            int row = mw + 16 * (t >> 1) + 8 * (t & 1) + g;
            int idx = kg * 128 + row;
            sm1[idx] = m1v[t]; sk1[idx] = k1v[t];
            sm2[idx] = m2v[t]; sk2[idx] = k2v[t];
        }
    }
    __syncthreads();
    if (tid < 128) {
        float a1 = sm1[tid], a2 = sm2[tid];
        int  ka1 = sk1[tid], ka2 = sk2[tid];
        merge2(a1, ka1, a2, ka2, sm1[128 + tid], sk1[128 + tid],
               sm2[128 + tid], sk2[128 + tid]);
        size_t rho = (size_t)(n0 + tid) * 4 + p;
        g_minD[rho] = a1;
        g_idx[rho]  = ka1;
        g_m2[rho]   = a2;
        g_k2[rho]   = ka2;
    }
}

// ---------------------------------------------------------------------------
// K1b: exact-fp32 argmin rescue for near-tie rows. One warp per rho.
__global__ void __launch_bounds__(128)
k_rescue(const float* __restrict__ z, const float* __restrict__ cb) {
    int w    = threadIdx.x >> 5;
    int lane = threadIdx.x & 31;
    int rho  = blockIdx.x * 4 + w;
    float m1 = g_minD[rho];
    float m2 = g_m2[rho];
    if (!(m2 - m1 < EPS_RESCUE)) return;     // g_idx already correct

    int k1 = g_idx[rho], k2 = g_k2[rho];
    int n = rho >> 2, p = rho & 3;
    int b = n / HW_, hw = n - b * HW_;
    const float* zr  = z + (size_t)(b * C_ + p * D_) * HW_ + hw;
    const float* c1r = cb + (size_t)(p * K_ + k1) * D_;
    const float* c2r = cb + (size_t)(p * K_ + k2) * D_;

    float a1 = 0.f, a2 = 0.f;
#pragma unroll
    for (int t = 0; t < 4; t++) {
        int j = lane + 32 * t;
        float zv = zr[(size_t)j * HW_];
        a1 = __fmaf_rn(zv, c1r[j], a1);
        a2 = __fmaf_rn(zv, c2r[j], a2);
    }
    for (int o = 16; o; o >>= 1) {
        a1 += __shfl_xor_sync(0xffffffffu, a1, o);
        a2 += __shfl_xor_sync(0xffffffffu, a2, o);
    }
    if (lane == 0) {
        float sz = g_szv[rho];
        float d1 = __fmaf_rn(-2.f, a1, __fadd_rn(sz, g_sc[p * K_ + k1]));
        float d2 = __fmaf_rn(-2.f, a2, __fadd_rn(sz, g_sc[p * K_ + k2]));
        int pick = (d1 < d2 || (d1 == d2 && k1 < k2)) ? k1 : k2;
        g_idx[rho] = pick;
    }
}

// ---------------------------------------------------------------------------
// K2: in-place softmax normalize. One 64-thread group per row (4 rows/CTA).
__global__ void __launch_bounds__(256)
k_norm(float* __restrict__ out) {
    int g      = threadIdx.x >> 6;
    int lane64 = threadIdx.x & 63;
    int rho    = blockIdx.x * 4 + g;
    float* row = out + PROB_OFF + (size_t)rho * 2048;
    float m = g_minD[rho];

    float e[32];
    float s = 0.f;
#pragma unroll 4
    for (int ii = 0; ii < 32; ii++) {
        float dist = row[lane64 + 64 * ii];
        float ev = expf(2.f * (m - dist));
        e[ii] = ev;
        s += ev;
    }
    for (int o = 16; o; o >>= 1) s += __shfl_down_sync(0xffffffffu, s, o);
    __shared__ float wsum[8];
    if ((threadIdx.x & 31) == 0) wsum[threadIdx.x >> 5] = s;
    __syncthreads();
    float S = wsum[2 * g] + wsum[2 * g + 1];
    float inv = 1.0f / S;
#pragma unroll 4
    for (int ii = 0; ii < 32; ii++) row[lane64 + 64 * ii] = e[ii] * inv;
}

// ---------------------------------------------------------------------------
// K3: zq_out (straight-through, fl(zf + fl(zq - zf))) + per-CTA loss partials.
__global__ void __launch_bounds__(256)
k_zq(const float* __restrict__ z, const float* __restrict__ cb,
     float* __restrict__ out) {
    __shared__ float cz[TN][D_];
    __shared__ int   sidx[TN];
    __shared__ float lred[256];

    const int tile = blockIdx.x;
    const int p    = blockIdx.y;
    const int tid  = threadIdx.x;
    const int n0   = tile * TN;

    if (tid < TN) sidx[tid] = g_idx[(n0 + tid) * 4 + p];
    __syncthreads();

    for (int e = tid; e < TN * (D_ / 4); e += 256) {
        int r  = e >> 5;
        int j4 = e & 31;
        float4 v = *(const float4*)(cb + ((size_t)(p * K_ + sidx[r]) * D_) + j4 * 4);
        cz[r][j4 * 4 + 0] = v.x; cz[r][j4 * 4 + 1] = v.y;
        cz[r][j4 * 4 + 2] = v.z; cz[r][j4 * 4 + 3] = v.w;
    }
    __syncthreads();

    float ls = 0.f;
    for (int e = tid; e < TN * D_; e += 256) {
        int j = e >> 6;
        int r = e & 63;
        int n = n0 + r;
        int b = n / HW_;
        int hw = n - b * HW_;
        size_t ga = (size_t)(b * C_ + p * D_ + j) * HW_ + hw;
        float zf = z[ga];
        float d  = __fsub_rn(cz[r][j], zf);
        out[ga]  = __fadd_rn(zf, d);
        ls = __fadd_rn(ls, __fmul_rn(d, d));
    }
    lred[tid] = ls;
    __syncthreads();
    for (int o = 128; o; o >>= 1) {
        if (tid < o) lred[tid] += lred[tid + o];
        __syncthreads();
    }
    if (tid == 0) g_losspart[p * NTILE + tile] = lred[0];
}

// ---------------------------------------------------------------------------
// K4: final deterministic loss reduction. q = m + fl(0.25*m).
__global__ void k_loss(float* __restrict__ out) {
    __shared__ float s[256];
    int tid = threadIdx.x;
    float a = 0.f;
    for (int e = tid; e < NTILE * P_; e += 256) a += g_losspart[e];
    s[tid] = a;
    __syncthreads();
    for (int o = 128; o; o >>= 1) {
        if (tid < o) s[tid] += s[tid + o];
        __syncthreads();
    }
    if (tid == 0) {
        float m = s[0] / 6422528.0f;
        out[LOSS_OFF] = __fadd_rn(m, __fmul_rn(0.25f, m));
    }
}

// ---------------------------------------------------------------------------
extern "C" void kernel_launch(void* const* d_in, const int* in_sizes, int n_in,
                              void* d_out, int out_size) {
    const float* z  = (const float*)d_in[0];   // [16,512,28,28]
    const float* cb = (const float*)d_in[1];   // [4,2048,128]
    float* out = (float*)d_out;

    const int smem_mma = SMEM_FLOATS * (int)sizeof(float);
    cudaFuncSetAttribute(k_mma, cudaFuncAttributeMaxDynamicSharedMemorySize, smem_mma);

    k_sc<<<32, 256>>>(cb);
    k_mma<<<dim3(MTILE, P_), 256, smem_mma>>>(z, cb, out);
    k_rescue<<<NP_ / 4, 128>>>(z, cb);
    k_norm<<<N_, 256>>>(out);
    k_zq<<<dim3(NTILE, P_), 256>>>(z, cb, out);
    k_loss<<<1, 256>>>(out);
}